// round 2
// baseline (speedup 1.0000x reference)
#include <cuda_runtime.h>

#define cB  2
#define cN  2065
#define cNP 2048
#define cNT 16
#define cE  512
#define cH  8
#define cE3 1536
#define NBH (cB*cH)
#define SCALE_QK 0.125f
#define EPS_BAL  1e-6f

// Scratch (static device globals: allocation-free)
__device__ float g_qkv[(size_t)cB * cN * cE3];   // ~25.4 MB
__device__ float g_oh [(size_t)cB * cN * cE];    // ~8.5 MB
__device__ float g_fac[(size_t)NBH * cN * 4];    // row factors f0,f1,f2,pad

// ---------------------------------------------------------------------------
// GEMM + bias: C[M,Nc] = A[M,K] @ W[K,Nc] + bias. 128x128 tile, BK=16,
// 256 threads, 8x8 per thread. Requires Nc % 128 == 0, K % 16 == 0.
// ---------------------------------------------------------------------------
__global__ __launch_bounds__(256)
void gemm_bias_kernel(const float* __restrict__ A, const float* __restrict__ W,
                      const float* __restrict__ bias, float* __restrict__ C,
                      int M, int Nc, int K) {
    __shared__ float As[16][132];   // [k][m]
    __shared__ float Ws[16][132];   // [k][n]
    const int t  = threadIdx.x;
    const int tx = t & 15, ty = t >> 4;
    const int m0 = blockIdx.y * 128, n0 = blockIdx.x * 128;

    const int ar = t >> 1, kg = (t & 1) * 8;  // A-tile load coords
    const int kr = t >> 4, wc = (t & 15) * 4; // W-tile load coords

    float acc[8][8] = {};

    for (int k0 = 0; k0 < K; k0 += 16) {
        float4 a0 = make_float4(0.f,0.f,0.f,0.f), a1 = a0;
        if (m0 + ar < M) {
            const float* p = &A[(size_t)(m0 + ar) * K + k0 + kg];
            a0 = *(const float4*)p;
            a1 = *(const float4*)(p + 4);
        }
        As[kg+0][ar] = a0.x; As[kg+1][ar] = a0.y; As[kg+2][ar] = a0.z; As[kg+3][ar] = a0.w;
        As[kg+4][ar] = a1.x; As[kg+5][ar] = a1.y; As[kg+6][ar] = a1.z; As[kg+7][ar] = a1.w;

        const float* wp = &W[(size_t)(k0 + kr) * Nc + n0];
        *(float4*)&Ws[kr][wc]      = *(const float4*)(wp + wc);
        *(float4*)&Ws[kr][wc + 64] = *(const float4*)(wp + wc + 64);
        __syncthreads();

        #pragma unroll
        for (int kk = 0; kk < 16; kk++) {
            float a[8], b[8];
            *(float4*)&a[0] = *(float4*)&As[kk][ty*8];
            *(float4*)&a[4] = *(float4*)&As[kk][ty*8+4];
            *(float4*)&b[0] = *(float4*)&Ws[kk][tx*8];
            *(float4*)&b[4] = *(float4*)&Ws[kk][tx*8+4];
            #pragma unroll
            for (int i = 0; i < 8; i++)
                #pragma unroll
                for (int j = 0; j < 8; j++)
                    acc[i][j] = fmaf(a[i], b[j], acc[i][j]);
        }
        __syncthreads();
    }

    #pragma unroll
    for (int i = 0; i < 8; i++) {
        int gr = m0 + ty*8 + i;
        if (gr >= M) continue;
        float* cp = &C[(size_t)gr * Nc + n0 + tx*8];
        const float* bp = &bias[n0 + tx*8];
        float4 r0, r1;
        r0.x = acc[i][0] + bp[0]; r0.y = acc[i][1] + bp[1];
        r0.z = acc[i][2] + bp[2]; r0.w = acc[i][3] + bp[3];
        r1.x = acc[i][4] + bp[4]; r1.y = acc[i][5] + bp[5];
        r1.z = acc[i][6] + bp[6]; r1.w = acc[i][7] + bp[7];
        *(float4*)cp       = r0;
        *(float4*)(cp + 4) = r1;
    }
}

// ---------------------------------------------------------------------------
// QK^T per (b,h): A_raw = SCALE * Q K^T. 128x128 output tile, full K=64
// staged once in smem (transposed [d][row]); 8x8 per thread.
// ---------------------------------------------------------------------------
extern __shared__ float dynsm[];

__global__ __launch_bounds__(256)
void qk_kernel(const float* __restrict__ qkv, float* __restrict__ A_raw) {
    float (*Qs)[132] = (float(*)[132])dynsm;              // [64][132]
    float (*Ks)[132] = (float(*)[132])(dynsm + 64*132);   // [64][132]
    const int bh = blockIdx.z, b = bh >> 3, h = bh & 7;
    const int n0 = blockIdx.y * 128, m0 = blockIdx.x * 128;
    const float* qb = qkv + (size_t)b * cN * cE3 + h * 64;
    const float* kb = qb + cE;
    const int t = threadIdx.x;

    #pragma unroll
    for (int i = 0; i < 8; i++) {
        int idx = t + i * 256;          // 2048 float4 per operand
        int row = idx >> 4, dq = (idx & 15) * 4;
        float4 qv = make_float4(0.f,0.f,0.f,0.f), kv = qv;
        if (n0 + row < cN) qv = *(const float4*)&qb[(size_t)(n0 + row) * cE3 + dq];
        if (m0 + row < cN) kv = *(const float4*)&kb[(size_t)(m0 + row) * cE3 + dq];
        Qs[dq+0][row] = qv.x; Qs[dq+1][row] = qv.y; Qs[dq+2][row] = qv.z; Qs[dq+3][row] = qv.w;
        Ks[dq+0][row] = kv.x; Ks[dq+1][row] = kv.y; Ks[dq+2][row] = kv.z; Ks[dq+3][row] = kv.w;
    }
    __syncthreads();

    const int tx = t & 15, ty = t >> 4;
    float acc[8][8] = {};
    #pragma unroll 8
    for (int kk = 0; kk < 64; kk++) {
        float a[8], b[8];
        *(float4*)&a[0] = *(float4*)&Qs[kk][ty*8];
        *(float4*)&a[4] = *(float4*)&Qs[kk][ty*8+4];
        *(float4*)&b[0] = *(float4*)&Ks[kk][tx*8];
        *(float4*)&b[4] = *(float4*)&Ks[kk][tx*8+4];
        #pragma unroll
        for (int i = 0; i < 8; i++)
            #pragma unroll
            for (int j = 0; j < 8; j++)
                acc[i][j] = fmaf(a[i], b[j], acc[i][j]);
    }

    const size_t base = (size_t)bh * cN * cN;
    #pragma unroll
    for (int i = 0; i < 8; i++) {
        int gr = n0 + ty*8 + i;
        if (gr >= cN) continue;
        float* rp = &A_raw[base + (size_t)gr * cN];
        #pragma unroll
        for (int j = 0; j < 8; j++) {
            int gc = m0 + tx*8 + j;
            if (gc < cN) rp[gc] = acc[i][j] * SCALE_QK;  // scalar: odd row stride
        }
    }
}

// ---------------------------------------------------------------------------
// Row stats: per (bh,n) row of A_raw, compute 3 balanced-softmax factors.
// ---------------------------------------------------------------------------
__inline__ __device__ float warpSum(float v) {
    #pragma unroll
    for (int o = 16; o > 0; o >>= 1) v += __shfl_down_sync(0xffffffffu, v, o);
    return v;
}

__global__ __launch_bounds__(256)
void stats_kernel(const float* __restrict__ A_raw, float* __restrict__ fac) {
    const size_t row = blockIdx.x;
    const float* src = A_raw + row * cN;
    const int t = threadIdx.x;
    __shared__ float red[4][8];
    __shared__ float s_ac;

    float sp = 0.f, sep = 0.f, st = 0.f, set = 0.f;
    for (int i = t; i < cN; i += 256) {
        float v = src[i];
        float e = __expf(v);
        if (i < cNP)            { sp += v; sep += e; }
        else if (i < cNP + cNT) { st += v; set += e; }
        else                    s_ac = v;
    }
    sp = warpSum(sp); sep = warpSum(sep); st = warpSum(st); set = warpSum(set);
    const int lane = t & 31, w = t >> 5;
    if (lane == 0) { red[0][w] = sp; red[1][w] = sep; red[2][w] = st; red[3][w] = set; }
    __syncthreads();
    if (t == 0) {
        float SP = 0.f, SEP = 0.f, ST = 0.f, SET = 0.f;
        #pragma unroll
        for (int i = 0; i < 8; i++) { SP += red[0][i]; SEP += red[1][i]; ST += red[2][i]; SET += red[3][i]; }
        float ep = __expf(SP / (float)cNP);
        float et = __expf(ST / (float)cNT);
        float ec = __expf(s_ac);
        float s  = ep + et + ec;
        float4 f;
        f.x = (ep / s) / (SEP + EPS_BAL);
        f.y = (et / s) / (SET + EPS_BAL);
        f.z = (ec / s) / (ec  + EPS_BAL);
        f.w = 0.f;
        *(float4*)&fac[row * 4] = f;
    }
}

// ---------------------------------------------------------------------------
// Fused A-materialize + AV GEMM per (b,h):
//   A[n,m] = expf(A_raw[n,m]) * fac[n][seg(m)]  (written to global)
//   OH[b,n,h*64+d] = sum_m A[n,m] * V[m,d]
// 128(n) x 64(d) tile per block, m-chunks of 64. 8x4 per thread.
// ---------------------------------------------------------------------------
__global__ __launch_bounds__(256)
void av_kernel(const float* __restrict__ A_raw, const float* __restrict__ qkv,
               const float* __restrict__ fac, float* __restrict__ A,
               float* __restrict__ OH) {
    float (*Ats)[132] = (float(*)[132])dynsm;                    // [64 m][132 n]
    float (*Vs)[68]   = (float(*)[68])(dynsm + 64*132);          // [64 m][68 d]
    float (*ff)[4]    = (float(*)[4])(dynsm + 64*132 + 64*68);   // [128][4]

    const int bh = blockIdx.y, b = bh >> 3, h = bh & 7;
    const int n0 = blockIdx.x * 128;
    const int t = threadIdx.x;

    if (t < 128) {
        int n = n0 + t;
        float4 f = make_float4(0.f,0.f,0.f,0.f);
        if (n < cN) f = *(const float4*)&fac[((size_t)bh * cN + n) * 4];
        *(float4*)&ff[t][0] = f;
    }
    __syncthreads();

    const float* Ar = A_raw + (size_t)bh * cN * cN;
    float*       Aw = A     + (size_t)bh * cN * cN;
    const float* vb = qkv + (size_t)b * cN * cE3 + 2 * cE + h * 64;
    const int tx = t & 15, ty = t >> 4;

    float acc[8][4] = {};

    for (int m0 = 0; m0 < cN; m0 += 64) {
        const bool pure = (m0 + 64 <= cNP);   // whole chunk in patch segment

        // --- A tile: read raw, exp+scale, write A, stage transposed ---
        #pragma unroll
        for (int i = 0; i < 8; i++) {
            int idx = t + i * 256;
            int row = idx >> 4, mq = (idx & 15) * 4;
            int n = n0 + row;
            float e0 = 0.f, e1 = 0.f, e2 = 0.f, e3 = 0.f;
            if (n < cN) {
                const float* rp = &Ar[(size_t)n * cN + m0 + mq];
                float*       wp = &Aw[(size_t)n * cN + m0 + mq];
                if (pure) {
                    float f0 = ff[row][0];
                    e0 = __expf(rp[0]) * f0;
                    e1 = __expf(rp[1]) * f0;
                    e2 = __expf(rp[2]) * f0;
                    e3 = __expf(rp[3]) * f0;
                    wp[0] = e0; wp[1] = e1; wp[2] = e2; wp[3] = e3;
                } else {
                    #pragma unroll
                    for (int j = 0; j < 4; j++) {
                        int m = m0 + mq + j;
                        if (m < cN) {
                            int seg = (m < cNP) ? 0 : ((m < cNP + cNT) ? 1 : 2);
                            float e = __expf(rp[j]) * ff[row][seg];
                            wp[j] = e;
                            if (j == 0) e0 = e; else if (j == 1) e1 = e;
                            else if (j == 2) e2 = e; else e3 = e;
                        }
                    }
                }
            }
            Ats[mq+0][row] = e0; Ats[mq+1][row] = e1;
            Ats[mq+2][row] = e2; Ats[mq+3][row] = e3;
        }

        // --- V tile ---
        #pragma unroll
        for (int i = 0; i < 4; i++) {
            int idx = t + i * 256;
            int row = idx >> 4, dq = (idx & 15) * 4;
            float4 v = make_float4(0.f,0.f,0.f,0.f);
            if (m0 + row < cN) v = *(const float4*)&vb[(size_t)(m0 + row) * cE3 + dq];
            *(float4*)&Vs[row][dq] = v;
        }
        __syncthreads();

        #pragma unroll 8
        for (int kk = 0; kk < 64; kk++) {
            float a[8], bv[4];
            *(float4*)&a[0]  = *(float4*)&Ats[kk][ty*8];
            *(float4*)&a[4]  = *(float4*)&Ats[kk][ty*8+4];
            *(float4*)&bv[0] = *(float4*)&Vs[kk][tx*4];
            #pragma unroll
            for (int i = 0; i < 8; i++)
                #pragma unroll
                for (int j = 0; j < 4; j++)
                    acc[i][j] = fmaf(a[i], bv[j], acc[i][j]);
        }
        __syncthreads();
    }

    #pragma unroll
    for (int i = 0; i < 8; i++) {
        int n = n0 + ty*8 + i;
        if (n >= cN) continue;
        float4 r;
        r.x = acc[i][0]; r.y = acc[i][1]; r.z = acc[i][2]; r.w = acc[i][3];
        *(float4*)&OH[((size_t)b * cN + n) * cE + h * 64 + tx * 4] = r;
    }
}

// ---------------------------------------------------------------------------
extern "C" void kernel_launch(void* const* d_in, const int* in_sizes, int n_in,
                              void* d_out, int out_size) {
    const float* x     = (const float*)d_in[0];
    const float* w_qkv = (const float*)d_in[1];
    const float* b_qkv = (const float*)d_in[2];
    const float* w_out = (const float*)d_in[3];
    const float* b_out = (const float*)d_in[4];

    float* out   = (float*)d_out;
    float* A     = out + (size_t)cB * cN * cE;
    float* A_raw = A   + (size_t)NBH * cN * cN;

    float *qkv = nullptr, *oh = nullptr, *facp = nullptr;
    cudaGetSymbolAddress((void**)&qkv,  g_qkv);
    cudaGetSymbolAddress((void**)&oh,   g_oh);
    cudaGetSymbolAddress((void**)&facp, g_fac);

    const int M = cB * cN;  // 4130
    const int QK_SMEM = 2 * 64 * 132 * 4;               // 67584 B
    const int AV_SMEM = (64*132 + 64*68 + 128*4) * 4;   // 53248 B
    cudaFuncSetAttribute(qk_kernel, cudaFuncAttributeMaxDynamicSharedMemorySize, QK_SMEM);
    cudaFuncSetAttribute(av_kernel, cudaFuncAttributeMaxDynamicSharedMemorySize, AV_SMEM);

    // 1) QKV projection
    gemm_bias_kernel<<<dim3(cE3/128, (M+127)/128), 256>>>(x, w_qkv, b_qkv, qkv, M, cE3, cE);
    // 2) A_raw = scale * Q K^T
    qk_kernel<<<dim3((cN+127)/128, (cN+127)/128, NBH), 256, QK_SMEM>>>(qkv, A_raw);
    // 3) Row factors
    stats_kernel<<<NBH * cN, 256>>>(A_raw, facp);
    // 4) A materialize + OH = A @ V
    av_kernel<<<dim3((cN+127)/128, NBH), 256, AV_SMEM>>>(A_raw, qkv, facp, A, oh);
    // 5) out = OH @ w_out + b_out
    gemm_bias_kernel<<<dim3(cE/128, (M+127)/128), 256>>>(oh, w_out, b_out, out, M, cE, cE);
}

// round 3
// speedup vs baseline: 1.0003x; 1.0003x over previous
#include <cuda_runtime.h>

#define cB  2
#define cN  2065
#define cNP 2048
#define cNT 16
#define cE  512
#define cH  8
#define cE3 1536
#define NBH (cB*cH)
#define SCALE_QK 0.125f
#define EPS_BAL  1e-6f

// Scratch (static device globals: allocation-free)
__device__ float g_qkv[(size_t)cB * cN * cE3];   // ~25.4 MB
__device__ float g_oh [(size_t)cB * cN * cE];    // ~8.5 MB
__device__ float g_fac[(size_t)NBH * cN * 4];    // row factors f0,f1,f2,pad

// ---------------------------------------------------------------------------
// GEMM + bias: C[M,Nc] = A[M,K] @ W[K,Nc] + bias. 128x128 tile, BK=16,
// 256 threads, 8x8 per thread. Requires Nc % 128 == 0, K % 16 == 0.
// ---------------------------------------------------------------------------
__global__ __launch_bounds__(256)
void gemm_bias_kernel(const float* __restrict__ A, const float* __restrict__ W,
                      const float* __restrict__ bias, float* __restrict__ C,
                      int M, int Nc, int K) {
    __shared__ float As[16][132];   // [k][m]
    __shared__ float Ws[16][132];   // [k][n]
    const int t  = threadIdx.x;
    const int tx = t & 15, ty = t >> 4;
    const int m0 = blockIdx.y * 128, n0 = blockIdx.x * 128;

    const int ar = t >> 1, kg = (t & 1) * 8;  // A-tile load coords
    const int kr = t >> 4, wc = (t & 15) * 4; // W-tile load coords

    float acc[8][8] = {};

    for (int k0 = 0; k0 < K; k0 += 16) {
        float4 a0 = make_float4(0.f,0.f,0.f,0.f), a1 = a0;
        if (m0 + ar < M) {
            const float* p = &A[(size_t)(m0 + ar) * K + k0 + kg];
            a0 = *(const float4*)p;
            a1 = *(const float4*)(p + 4);
        }
        As[kg+0][ar] = a0.x; As[kg+1][ar] = a0.y; As[kg+2][ar] = a0.z; As[kg+3][ar] = a0.w;
        As[kg+4][ar] = a1.x; As[kg+5][ar] = a1.y; As[kg+6][ar] = a1.z; As[kg+7][ar] = a1.w;

        const float* wp = &W[(size_t)(k0 + kr) * Nc + n0];
        *(float4*)&Ws[kr][wc]      = *(const float4*)(wp + wc);
        *(float4*)&Ws[kr][wc + 64] = *(const float4*)(wp + wc + 64);
        __syncthreads();

        #pragma unroll
        for (int kk = 0; kk < 16; kk++) {
            float a[8], b[8];
            *(float4*)&a[0] = *(float4*)&As[kk][ty*8];
            *(float4*)&a[4] = *(float4*)&As[kk][ty*8+4];
            *(float4*)&b[0] = *(float4*)&Ws[kk][tx*8];
            *(float4*)&b[4] = *(float4*)&Ws[kk][tx*8+4];
            #pragma unroll
            for (int i = 0; i < 8; i++)
                #pragma unroll
                for (int j = 0; j < 8; j++)
                    acc[i][j] = fmaf(a[i], b[j], acc[i][j]);
        }
        __syncthreads();
    }

    #pragma unroll
    for (int i = 0; i < 8; i++) {
        int gr = m0 + ty*8 + i;
        if (gr >= M) continue;
        float* cp = &C[(size_t)gr * Nc + n0 + tx*8];
        const float* bp = &bias[n0 + tx*8];
        float4 r0, r1;
        r0.x = acc[i][0] + bp[0]; r0.y = acc[i][1] + bp[1];
        r0.z = acc[i][2] + bp[2]; r0.w = acc[i][3] + bp[3];
        r1.x = acc[i][4] + bp[4]; r1.y = acc[i][5] + bp[5];
        r1.z = acc[i][6] + bp[6]; r1.w = acc[i][7] + bp[7];
        *(float4*)cp       = r0;
        *(float4*)(cp + 4) = r1;
    }
}

// ---------------------------------------------------------------------------
// QK^T per (b,h): A_raw = SCALE * Q K^T. 128x128 output tile, full K=64
// staged once in smem (transposed [d][row]); 8x8 per thread.
// ---------------------------------------------------------------------------
extern __shared__ float dynsm[];

__global__ __launch_bounds__(256)
void qk_kernel(const float* __restrict__ qkv, float* __restrict__ A_raw) {
    float (*Qs)[132] = (float(*)[132])dynsm;              // [64][132]
    float (*Ks)[132] = (float(*)[132])(dynsm + 64*132);   // [64][132]
    const int bh = blockIdx.z, b = bh >> 3, h = bh & 7;
    const int n0 = blockIdx.y * 128, m0 = blockIdx.x * 128;
    const float* qb = qkv + (size_t)b * cN * cE3 + h * 64;
    const float* kb = qb + cE;
    const int t = threadIdx.x;

    #pragma unroll
    for (int i = 0; i < 8; i++) {
        int idx = t + i * 256;          // 2048 float4 per operand
        int row = idx >> 4, dq = (idx & 15) * 4;
        float4 qv = make_float4(0.f,0.f,0.f,0.f), kv = qv;
        if (n0 + row < cN) qv = *(const float4*)&qb[(size_t)(n0 + row) * cE3 + dq];
        if (m0 + row < cN) kv = *(const float4*)&kb[(size_t)(m0 + row) * cE3 + dq];
        Qs[dq+0][row] = qv.x; Qs[dq+1][row] = qv.y; Qs[dq+2][row] = qv.z; Qs[dq+3][row] = qv.w;
        Ks[dq+0][row] = kv.x; Ks[dq+1][row] = kv.y; Ks[dq+2][row] = kv.z; Ks[dq+3][row] = kv.w;
    }
    __syncthreads();

    const int tx = t & 15, ty = t >> 4;
    float acc[8][8] = {};
    #pragma unroll 8
    for (int kk = 0; kk < 64; kk++) {
        float a[8], b[8];
        *(float4*)&a[0] = *(float4*)&Qs[kk][ty*8];
        *(float4*)&a[4] = *(float4*)&Qs[kk][ty*8+4];
        *(float4*)&b[0] = *(float4*)&Ks[kk][tx*8];
        *(float4*)&b[4] = *(float4*)&Ks[kk][tx*8+4];
        #pragma unroll
        for (int i = 0; i < 8; i++)
            #pragma unroll
            for (int j = 0; j < 8; j++)
                acc[i][j] = fmaf(a[i], b[j], acc[i][j]);
    }

    const size_t base = (size_t)bh * cN * cN;
    #pragma unroll
    for (int i = 0; i < 8; i++) {
        int gr = n0 + ty*8 + i;
        if (gr >= cN) continue;
        float* rp = &A_raw[base + (size_t)gr * cN];
        #pragma unroll
        for (int j = 0; j < 8; j++) {
            int gc = m0 + tx*8 + j;
            if (gc < cN) rp[gc] = acc[i][j] * SCALE_QK;  // scalar: odd row stride
        }
    }
}

// ---------------------------------------------------------------------------
// Row stats: per (bh,n) row of A_raw, compute 3 balanced-softmax factors.
// ---------------------------------------------------------------------------
__inline__ __device__ float warpSum(float v) {
    #pragma unroll
    for (int o = 16; o > 0; o >>= 1) v += __shfl_down_sync(0xffffffffu, v, o);
    return v;
}

__global__ __launch_bounds__(256)
void stats_kernel(const float* __restrict__ A_raw, float* __restrict__ fac) {
    const size_t row = blockIdx.x;
    const float* src = A_raw + row * cN;
    const int t = threadIdx.x;
    __shared__ float red[4][8];
    __shared__ float s_ac;

    float sp = 0.f, sep = 0.f, st = 0.f, set = 0.f;
    for (int i = t; i < cN; i += 256) {
        float v = src[i];
        float e = __expf(v);
        if (i < cNP)            { sp += v; sep += e; }
        else if (i < cNP + cNT) { st += v; set += e; }
        else                    s_ac = v;
    }
    sp = warpSum(sp); sep = warpSum(sep); st = warpSum(st); set = warpSum(set);
    const int lane = t & 31, w = t >> 5;
    if (lane == 0) { red[0][w] = sp; red[1][w] = sep; red[2][w] = st; red[3][w] = set; }
    __syncthreads();
    if (t == 0) {
        float SP = 0.f, SEP = 0.f, ST = 0.f, SET = 0.f;
        #pragma unroll
        for (int i = 0; i < 8; i++) { SP += red[0][i]; SEP += red[1][i]; ST += red[2][i]; SET += red[3][i]; }
        float ep = __expf(SP / (float)cNP);
        float et = __expf(ST / (float)cNT);
        float ec = __expf(s_ac);
        float s  = ep + et + ec;
        float4 f;
        f.x = (ep / s) / (SEP + EPS_BAL);
        f.y = (et / s) / (SET + EPS_BAL);
        f.z = (ec / s) / (ec  + EPS_BAL);
        f.w = 0.f;
        *(float4*)&fac[row * 4] = f;
    }
}

// ---------------------------------------------------------------------------
// Fused A-materialize + AV GEMM per (b,h):
//   A[n,m] = expf(A_raw[n,m]) * fac[n][seg(m)]  (written to global)
//   OH[b,n,h*64+d] = sum_m A[n,m] * V[m,d]
// 128(n) x 64(d) tile per block, m-chunks of 64. 8x4 per thread.
// ---------------------------------------------------------------------------
__global__ __launch_bounds__(256)
void av_kernel(const float* __restrict__ A_raw, const float* __restrict__ qkv,
               const float* __restrict__ fac, float* __restrict__ A,
               float* __restrict__ OH) {
    float (*Ats)[132] = (float(*)[132])dynsm;                    // [64 m][132 n]
    float (*Vs)[68]   = (float(*)[68])(dynsm + 64*132);          // [64 m][68 d]
    float (*ff)[4]    = (float(*)[4])(dynsm + 64*132 + 64*68);   // [128][4]

    const int bh = blockIdx.y, b = bh >> 3, h = bh & 7;
    const int n0 = blockIdx.x * 128;
    const int t = threadIdx.x;

    if (t < 128) {
        int n = n0 + t;
        float4 f = make_float4(0.f,0.f,0.f,0.f);
        if (n < cN) f = *(const float4*)&fac[((size_t)bh * cN + n) * 4];
        *(float4*)&ff[t][0] = f;
    }
    __syncthreads();

    const float* Ar = A_raw + (size_t)bh * cN * cN;
    float*       Aw = A     + (size_t)bh * cN * cN;
    const float* vb = qkv + (size_t)b * cN * cE3 + 2 * cE + h * 64;
    const int tx = t & 15, ty = t >> 4;

    float acc[8][4] = {};

    for (int m0 = 0; m0 < cN; m0 += 64) {
        const bool pure = (m0 + 64 <= cNP);   // whole chunk in patch segment

        // --- A tile: read raw, exp+scale, write A, stage transposed ---
        #pragma unroll
        for (int i = 0; i < 8; i++) {
            int idx = t + i * 256;
            int row = idx >> 4, mq = (idx & 15) * 4;
            int n = n0 + row;
            float e0 = 0.f, e1 = 0.f, e2 = 0.f, e3 = 0.f;
            if (n < cN) {
                const float* rp = &Ar[(size_t)n * cN + m0 + mq];
                float*       wp = &Aw[(size_t)n * cN + m0 + mq];
                if (pure) {
                    float f0 = ff[row][0];
                    e0 = __expf(rp[0]) * f0;
                    e1 = __expf(rp[1]) * f0;
                    e2 = __expf(rp[2]) * f0;
                    e3 = __expf(rp[3]) * f0;
                    wp[0] = e0; wp[1] = e1; wp[2] = e2; wp[3] = e3;
                } else {
                    #pragma unroll
                    for (int j = 0; j < 4; j++) {
                        int m = m0 + mq + j;
                        if (m < cN) {
                            int seg = (m < cNP) ? 0 : ((m < cNP + cNT) ? 1 : 2);
                            float e = __expf(rp[j]) * ff[row][seg];
                            wp[j] = e;
                            if (j == 0) e0 = e; else if (j == 1) e1 = e;
                            else if (j == 2) e2 = e; else e3 = e;
                        }
                    }
                }
            }
            Ats[mq+0][row] = e0; Ats[mq+1][row] = e1;
            Ats[mq+2][row] = e2; Ats[mq+3][row] = e3;
        }

        // --- V tile ---
        #pragma unroll
        for (int i = 0; i < 4; i++) {
            int idx = t + i * 256;
            int row = idx >> 4, dq = (idx & 15) * 4;
            float4 v = make_float4(0.f,0.f,0.f,0.f);
            if (m0 + row < cN) v = *(const float4*)&vb[(size_t)(m0 + row) * cE3 + dq];
            *(float4*)&Vs[row][dq] = v;
        }
        __syncthreads();

        #pragma unroll 8
        for (int kk = 0; kk < 64; kk++) {
            float a[8], bv[4];
            *(float4*)&a[0]  = *(float4*)&Ats[kk][ty*8];
            *(float4*)&a[4]  = *(float4*)&Ats[kk][ty*8+4];
            *(float4*)&bv[0] = *(float4*)&Vs[kk][tx*4];
            #pragma unroll
            for (int i = 0; i < 8; i++)
                #pragma unroll
                for (int j = 0; j < 4; j++)
                    acc[i][j] = fmaf(a[i], bv[j], acc[i][j]);
        }
        __syncthreads();
    }

    #pragma unroll
    for (int i = 0; i < 8; i++) {
        int n = n0 + ty*8 + i;
        if (n >= cN) continue;
        float4 r;
        r.x = acc[i][0]; r.y = acc[i][1]; r.z = acc[i][2]; r.w = acc[i][3];
        *(float4*)&OH[((size_t)b * cN + n) * cE + h * 64 + tx * 4] = r;
    }
}

// ---------------------------------------------------------------------------
extern "C" void kernel_launch(void* const* d_in, const int* in_sizes, int n_in,
                              void* d_out, int out_size) {
    const float* x     = (const float*)d_in[0];
    const float* w_qkv = (const float*)d_in[1];
    const float* b_qkv = (const float*)d_in[2];
    const float* w_out = (const float*)d_in[3];
    const float* b_out = (const float*)d_in[4];

    float* out   = (float*)d_out;
    float* A     = out + (size_t)cB * cN * cE;
    float* A_raw = A   + (size_t)NBH * cN * cN;

    float *qkv = nullptr, *oh = nullptr, *facp = nullptr;
    cudaGetSymbolAddress((void**)&qkv,  g_qkv);
    cudaGetSymbolAddress((void**)&oh,   g_oh);
    cudaGetSymbolAddress((void**)&facp, g_fac);

    const int M = cB * cN;  // 4130
    const int QK_SMEM = 2 * 64 * 132 * 4;               // 67584 B
    const int AV_SMEM = (64*132 + 64*68 + 128*4) * 4;   // 53248 B
    cudaFuncSetAttribute(qk_kernel, cudaFuncAttributeMaxDynamicSharedMemorySize, QK_SMEM);
    cudaFuncSetAttribute(av_kernel, cudaFuncAttributeMaxDynamicSharedMemorySize, AV_SMEM);

    // 1) QKV projection
    gemm_bias_kernel<<<dim3(cE3/128, (M+127)/128), 256>>>(x, w_qkv, b_qkv, qkv, M, cE3, cE);
    // 2) A_raw = scale * Q K^T
    qk_kernel<<<dim3((cN+127)/128, (cN+127)/128, NBH), 256, QK_SMEM>>>(qkv, A_raw);
    // 3) Row factors
    stats_kernel<<<NBH * cN, 256>>>(A_raw, facp);
    // 4) A materialize + OH = A @ V
    av_kernel<<<dim3((cN+127)/128, NBH), 256, AV_SMEM>>>(A_raw, qkv, facp, A, oh);
    // 5) out = OH @ w_out + b_out
    gemm_bias_kernel<<<dim3(cE/128, (M+127)/128), 256>>>(oh, w_out, b_out, out, M, cE, cE);
}

// round 5
// speedup vs baseline: 1.1084x; 1.1080x over previous
#include <cuda_runtime.h>
#include <cstdint>

#define cB  2
#define cN  2065
#define cNP 2048
#define cNT 16
#define cE  512
#define cH  8
#define cE3 1536
#define NBH (cB*cH)
#define SCALE_QK 0.125f
#define EPS_BAL  1e-6f
#define PROWS 2176
#define PSTR  72

__device__ float g_qkv [(size_t)cB * cN * cE3];
__device__ float g_oh  [(size_t)cB * cN * cE];
__device__ float g_fac [(size_t)NBH * cN * 4];
__device__ float g_part[(size_t)NBH * PROWS * PSTR];

__device__ __forceinline__ uint32_t f2tf32(float x) {
    uint32_t r; asm("cvt.rna.tf32.f32 %0, %1;" : "=r"(r) : "f"(x)); return r;
}
__device__ __forceinline__ void mma_tf32(float* c, uint32_t a0, uint32_t a1,
                                         uint32_t a2, uint32_t a3,
                                         uint32_t b0, uint32_t b1) {
    asm volatile(
        "mma.sync.aligned.m16n8k8.row.col.f32.tf32.tf32.f32 "
        "{%0,%1,%2,%3}, {%4,%5,%6,%7}, {%8,%9}, {%0,%1,%2,%3};"
        : "+f"(c[0]), "+f"(c[1]), "+f"(c[2]), "+f"(c[3])
        : "r"(a0), "r"(a1), "r"(a2), "r"(a3), "r"(b0), "r"(b1));
}

extern __shared__ float dynsm[];

// ------------------------------------------------------- FP32 GEMM + bias
__global__ __launch_bounds__(256)
void gemm_bias_kernel(const float* __restrict__ A, const float* __restrict__ W,
                      const float* __restrict__ bias, float* __restrict__ C,
                      int M, int Nc, int K) {
    __shared__ float As[16][132];
    __shared__ float Ws[16][132];
    const int t  = threadIdx.x;
    const int tx = t & 15, ty = t >> 4;
    const int m0 = blockIdx.y * 128, n0 = blockIdx.x * 128;
    const int ar = t >> 1, kg = (t & 1) * 8;
    const int kr = t >> 4, wc = (t & 15) * 4;

    float acc[8][8] = {};
    for (int k0 = 0; k0 < K; k0 += 16) {
        float4 a0 = make_float4(0.f,0.f,0.f,0.f), a1 = a0;
        if (m0 + ar < M) {
            const float* p = &A[(size_t)(m0 + ar) * K + k0 + kg];
            a0 = *(const float4*)p; a1 = *(const float4*)(p + 4);
        }
        As[kg+0][ar] = a0.x; As[kg+1][ar] = a0.y; As[kg+2][ar] = a0.z; As[kg+3][ar] = a0.w;
        As[kg+4][ar] = a1.x; As[kg+5][ar] = a1.y; As[kg+6][ar] = a1.z; As[kg+7][ar] = a1.w;
        const float* wp = &W[(size_t)(k0 + kr) * Nc + n0];
        *(float4*)&Ws[kr][wc]      = *(const float4*)(wp + wc);
        *(float4*)&Ws[kr][wc + 64] = *(const float4*)(wp + wc + 64);
        __syncthreads();
        #pragma unroll
        for (int kk = 0; kk < 16; kk++) {
            float a[8], b[8];
            *(float4*)&a[0] = *(float4*)&As[kk][ty*8];
            *(float4*)&a[4] = *(float4*)&As[kk][ty*8+4];
            *(float4*)&b[0] = *(float4*)&Ws[kk][tx*8];
            *(float4*)&b[4] = *(float4*)&Ws[kk][tx*8+4];
            #pragma unroll
            for (int i = 0; i < 8; i++)
                #pragma unroll
                for (int j = 0; j < 8; j++)
                    acc[i][j] = fmaf(a[i], b[j], acc[i][j]);
        }
        __syncthreads();
    }
    #pragma unroll
    for (int i = 0; i < 8; i++) {
        int gr = m0 + ty*8 + i;
        if (gr >= M) continue;
        float* cp = &C[(size_t)gr * Nc + n0 + tx*8];
        const float* bp = &bias[n0 + tx*8];
        float4 r0, r1;
        r0.x = acc[i][0]+bp[0]; r0.y = acc[i][1]+bp[1]; r0.z = acc[i][2]+bp[2]; r0.w = acc[i][3]+bp[3];
        r1.x = acc[i][4]+bp[4]; r1.y = acc[i][5]+bp[5]; r1.z = acc[i][6]+bp[6]; r1.w = acc[i][7]+bp[7];
        *(float4*)cp = r0; *(float4*)(cp+4) = r1;
    }
}

// ------------------------------- tf32 mma.sync QK^T + fused segment partials
// Block: 128(n) x 128(m) tile. 8 warps = 2(row) x 4(col); warp tile 64x32.
__global__ __launch_bounds__(256)
void qk_kernel(const float* __restrict__ qkv, float* __restrict__ A_raw,
               float* __restrict__ part) {
    const int t = threadIdx.x, lane = t & 31, wid = t >> 5;
    const int wrow = wid >> 2, wcol = wid & 3;
    const int bh = blockIdx.z, b = bh >> 3, h = bh & 7;
    const int n0 = blockIdx.y * 128;
    const int mtile = blockIdx.x, m0 = mtile * 128;

    uint32_t* qs = (uint32_t*)dynsm;       // [128][68] tf32 bits
    uint32_t* ks = qs + 128 * 68;          // [128][68]
    float* res = dynsm;                    // alias for output bounce [128][132]

    const float* qb = qkv + (size_t)b * cN * cE3 + h * 64;
    const float* kb = qb + cE;

    #pragma unroll
    for (int i = 0; i < 8; i++) {          // 128 rows x 16 float4 per operand
        int idx = t + i * 256;
        int row = idx >> 4, q4 = idx & 15;
        float4 qv = make_float4(0.f,0.f,0.f,0.f), kv = qv;
        if (n0 + row < cN) qv = *(const float4*)&qb[(size_t)(n0+row)*cE3 + q4*4];
        if (m0 + row < cN) kv = *(const float4*)&kb[(size_t)(m0+row)*cE3 + q4*4];
        uint4 qu = make_uint4(f2tf32(qv.x), f2tf32(qv.y), f2tf32(qv.z), f2tf32(qv.w));
        uint4 ku = make_uint4(f2tf32(kv.x), f2tf32(kv.y), f2tf32(kv.z), f2tf32(kv.w));
        *(uint4*)&qs[row*68 + q4*4] = qu;
        *(uint4*)&ks[row*68 + q4*4] = ku;
    }
    __syncthreads();

    float acc[4][4][4] = {};
    #pragma unroll
    for (int kk = 0; kk < 8; kk++) {
        const int k0 = kk * 8;
        uint32_t a[4][4], bq[4][2];
        #pragma unroll
        for (int mt = 0; mt < 4; mt++) {
            int r = wrow*64 + mt*16 + (lane >> 2);
            a[mt][0] = qs[r*68     + k0     + (lane & 3)];
            a[mt][1] = qs[(r+8)*68 + k0     + (lane & 3)];
            a[mt][2] = qs[r*68     + k0 + 4 + (lane & 3)];
            a[mt][3] = qs[(r+8)*68 + k0 + 4 + (lane & 3)];
        }
        #pragma unroll
        for (int nt = 0; nt < 4; nt++) {
            int cc = wcol*32 + nt*8 + (lane >> 2);
            bq[nt][0] = ks[cc*68 + k0     + (lane & 3)];
            bq[nt][1] = ks[cc*68 + k0 + 4 + (lane & 3)];
        }
        #pragma unroll
        for (int mt = 0; mt < 4; mt++)
            #pragma unroll
            for (int nt = 0; nt < 4; nt++)
                mma_tf32(acc[mt][nt], a[mt][0], a[mt][1], a[mt][2], a[mt][3],
                         bq[nt][0], bq[nt][1]);
    }
    __syncthreads();   // done reading qs/ks; res aliases them

    #pragma unroll
    for (int mt = 0; mt < 4; mt++) {
        int r = wrow*64 + mt*16 + (lane >> 2);
        #pragma unroll
        for (int nt = 0; nt < 4; nt++) {
            int cc = wcol*32 + nt*8 + (lane & 3)*2;
            *(float2*)&res[r*132 + cc]     = make_float2(acc[mt][nt][0], acc[mt][nt][1]);
            *(float2*)&res[(r+8)*132 + cc] = make_float2(acc[mt][nt][2], acc[mt][nt][3]);
        }
    }
    __syncthreads();

    // Segment partials: 2 threads per row, 64 cols each.
    {
        int row = t >> 1, cbase = (t & 1) * 64;
        float sp = 0.f, sep = 0.f, st = 0.f, set = 0.f, vc = 0.f;
        if (n0 + row < cN) {
            if (mtile < 16) {              // entire tile inside patch segment
                #pragma unroll 4
                for (int j = 0; j < 64; j++) {
                    float v = res[row*132 + cbase + j] * SCALE_QK;
                    sp += v; sep += __expf(v);
                }
            } else if (cbase == 0) {       // table cols 0..15, cls col 16
                for (int j = 0; j < 16; j++) {
                    float v = res[row*132 + j] * SCALE_QK;
                    st += v; set += __expf(v);
                }
                vc = res[row*132 + 16] * SCALE_QK;
            }
        }
        sp  += __shfl_xor_sync(0xffffffffu, sp,  1);
        sep += __shfl_xor_sync(0xffffffffu, sep, 1);
        st  += __shfl_xor_sync(0xffffffffu, st,  1);
        set += __shfl_xor_sync(0xffffffffu, set, 1);
        vc  += __shfl_xor_sync(0xffffffffu, vc,  1);
        if (!(t & 1) && (n0 + row) < cN) {
            float* pp = &part[((size_t)bh * PROWS + n0 + row) * PSTR + mtile * 4];
            pp[0] = sp; pp[1] = sep; pp[2] = st; pp[3] = set;
            if (mtile == 16)
                part[((size_t)bh * PROWS + n0 + row) * PSTR + 68] = vc;
        }
    }

    // Coalesced A_raw stores
    const size_t arbase = (size_t)bh * cN * cN;
    for (int i = 0; i < 64; i++) {
        int idx = t + i * 256;
        int r = idx >> 7, c = idx & 127;
        int gr = n0 + r, gc = m0 + c;
        if (gr < cN && gc < cN)
            A_raw[arbase + (size_t)gr * cN + gc] = res[r*132 + c] * SCALE_QK;
    }
}

// ------------------------------------------------------------ finalize fac
__global__ void finalize_kernel(const float* __restrict__ part, float* __restrict__ fac) {
    int idx = blockIdx.x * 256 + threadIdx.x;
    if (idx >= NBH * cN) return;
    int bh = idx / cN, n = idx - bh * cN;
    const float* p = part + ((size_t)bh * PROWS + n) * PSTR;
    float SP = 0.f, SEP = 0.f, ST = 0.f, SET = 0.f;
    #pragma unroll
    for (int mt = 0; mt < 17; mt++) {
        SP += p[mt*4]; SEP += p[mt*4+1]; ST += p[mt*4+2]; SET += p[mt*4+3];
    }
    float vc = p[68];
    float ep = __expf(SP * (1.f / (float)cNP));
    float et = __expf(ST * (1.f / (float)cNT));
    float ec = __expf(vc);
    float s = ep + et + ec;
    float* fp = &fac[(size_t)idx * 4];
    fp[0] = (ep / s) / (SEP + EPS_BAL);
    fp[1] = (et / s) / (SET + EPS_BAL);
    fp[2] = (ec / s) / (ec  + EPS_BAL);
    fp[3] = 0.f;
}

// ------------------------- tf32 mma.sync AV + A-materialize (fused epilogue)
// Block: 128(n) x 64(d). 8 warps = 4(row) x 2(col); warp tile 32x32.
__global__ __launch_bounds__(256)
void av_kernel(const float* __restrict__ A_raw, const float* __restrict__ qkv,
               const float* __restrict__ fac, float* __restrict__ A,
               float* __restrict__ OH) {
    __shared__ float4 ff[128];
    const int t = threadIdx.x, lane = t & 31, wid = t >> 5;
    const int wrow = wid >> 1, wcol = wid & 1;
    const int bh = blockIdx.y, b = bh >> 3, h = bh & 7;
    const int n0 = blockIdx.x * 128;

    uint32_t* as = (uint32_t*)dynsm;       // [128][132] tf32 bits
    uint32_t* vt = as + 128 * 132;         // [64][132]  V^T tf32 bits

    if (t < 128) {
        int n = n0 + t;
        ff[t] = (n < cN) ? *(const float4*)&fac[((size_t)bh * cN + n) * 4]
                         : make_float4(0.f, 0.f, 0.f, 0.f);
    }
    __syncthreads();

    const float* Ar = A_raw + (size_t)bh * cN * cN;
    float*       Aw = A     + (size_t)bh * cN * cN;
    const float* vb = qkv + (size_t)b * cN * cE3 + 2 * cE + h * 64;

    float acc[2][4][4] = {};

    for (int c = 0; c < 17; c++) {
        const int m0 = c * 128;
        if (c) __syncthreads();   // previous chunk's mma reads are done

        for (int i = 0; i < 64; i++) {     // A: read raw, exp*fac, write A, stage
            int idx = t + i * 256;
            int row = idx >> 7, col = idx & 127;
            int n = n0 + row, m = m0 + col;
            float e = 0.f;
            if (n < cN && m < cN) {
                float v = Ar[(size_t)n * cN + m];
                float f = (c < 16) ? ff[row].x : ((col < 16) ? ff[row].y : ff[row].z);
                e = __expf(v) * f;
                Aw[(size_t)n * cN + m] = e;
            }
            as[row*132 + col] = f2tf32(e);
        }
        for (int i = 0; i < 32; i++) {     // V^T stage: [d][m]
            int idx = t + i * 256;
            int ml = idx >> 6, d = idx & 63;
            float v = (m0 + ml < cN) ? vb[(size_t)(m0 + ml) * cE3 + d] : 0.f;
            vt[d*132 + ml] = f2tf32(v);
        }
        __syncthreads();

        #pragma unroll
        for (int kk = 0; kk < 16; kk++) {
            const int k0 = kk * 8;
            uint32_t a[2][4], bq[4][2];
            #pragma unroll
            for (int mt = 0; mt < 2; mt++) {
                int r = wrow*32 + mt*16 + (lane >> 2);
                a[mt][0] = as[r*132     + k0     + (lane & 3)];
                a[mt][1] = as[(r+8)*132 + k0     + (lane & 3)];
                a[mt][2] = as[r*132     + k0 + 4 + (lane & 3)];
                a[mt][3] = as[(r+8)*132 + k0 + 4 + (lane & 3)];
            }
            #pragma unroll
            for (int nt = 0; nt < 4; nt++) {
                int dd = wcol*32 + nt*8 + (lane >> 2);
                bq[nt][0] = vt[dd*132 + k0     + (lane & 3)];
                bq[nt][1] = vt[dd*132 + k0 + 4 + (lane & 3)];
            }
            #pragma unroll
            for (int mt = 0; mt < 2; mt++)
                #pragma unroll
                for (int nt = 0; nt < 4; nt++)
                    mma_tf32(acc[mt][nt], a[mt][0], a[mt][1], a[mt][2], a[mt][3],
                             bq[nt][0], bq[nt][1]);
        }
    }

    #pragma unroll
    for (int mt = 0; mt < 2; mt++) {
        #pragma unroll
        for (int nt = 0; nt < 4; nt++) {
            int n = n0 + wrow*32 + mt*16 + (lane >> 2);
            int d = wcol*32 + nt*8 + (lane & 3)*2;
            if (n < cN)
                *(float2*)&OH[((size_t)b * cN + n) * cE + h*64 + d] =
                    make_float2(acc[mt][nt][0], acc[mt][nt][1]);
            if (n + 8 < cN)
                *(float2*)&OH[((size_t)b * cN + n + 8) * cE + h*64 + d] =
                    make_float2(acc[mt][nt][2], acc[mt][nt][3]);
        }
    }
}

// ---------------------------------------------------------------------------
extern "C" void kernel_launch(void* const* d_in, const int* in_sizes, int n_in,
                              void* d_out, int out_size) {
    const float* x     = (const float*)d_in[0];
    const float* w_qkv = (const float*)d_in[1];
    const float* b_qkv = (const float*)d_in[2];
    const float* w_out = (const float*)d_in[3];
    const float* b_out = (const float*)d_in[4];

    float* out   = (float*)d_out;
    float* A     = out + (size_t)cB * cN * cE;
    float* A_raw = A   + (size_t)NBH * cN * cN;

    float *qkv = nullptr, *oh = nullptr, *facp = nullptr, *partp = nullptr;
    cudaGetSymbolAddress((void**)&qkv,   g_qkv);
    cudaGetSymbolAddress((void**)&oh,    g_oh);
    cudaGetSymbolAddress((void**)&facp,  g_fac);
    cudaGetSymbolAddress((void**)&partp, g_part);

    const int M = cB * cN;
    const int QK_SMEM = 2 * 128 * 68 * 4;            // 69632 B
    const int AV_SMEM = (128 * 132 + 64 * 132) * 4;  // 101376 B
    cudaFuncSetAttribute(qk_kernel, cudaFuncAttributeMaxDynamicSharedMemorySize, QK_SMEM);
    cudaFuncSetAttribute(av_kernel, cudaFuncAttributeMaxDynamicSharedMemorySize, AV_SMEM);

    gemm_bias_kernel<<<dim3(cE3/128, (M+127)/128), 256>>>(x, w_qkv, b_qkv, qkv, M, cE3, cE);
    qk_kernel<<<dim3(17, 17, NBH), 256, QK_SMEM>>>(qkv, A_raw, partp);
    finalize_kernel<<<(NBH*cN + 255)/256, 256>>>(partp, facp);
    av_kernel<<<dim3(17, NBH), 256, AV_SMEM>>>(A_raw, qkv, facp, A, oh);
    gemm_bias_kernel<<<dim3(cE/128, (M+127)/128), 256>>>(oh, w_out, b_out, out, M, cE, cE);
}

// round 6
// speedup vs baseline: 1.7693x; 1.5964x over previous
#include <cuda_runtime.h>
#include <cstdint>

#define cB  2
#define cN  2065
#define cNP 2048
#define cNT 16
#define cE  512
#define cH  8
#define cE3 1536
#define NBH (cB*cH)
#define SCALE_QK 0.125f
#define EPS_BAL  1e-6f
#define PROWS 2176
#define PSTR  72
#define NCH   33     // ceil(2065/64) k-chunks in avg

__device__ float g_qkv [(size_t)cB * cN * cE3];
__device__ float g_oh  [(size_t)cB * cN * cE];
__device__ float g_fac [(size_t)NBH * cN * 4];
__device__ float g_part[(size_t)NBH * PROWS * PSTR];

__device__ __forceinline__ uint32_t f2tf32(float x) {
    uint32_t r; asm("cvt.rna.tf32.f32 %0, %1;" : "=r"(r) : "f"(x)); return r;
}
__device__ __forceinline__ void mma_tf32(float* c, uint32_t a0, uint32_t a1,
                                         uint32_t a2, uint32_t a3,
                                         uint32_t b0, uint32_t b1) {
    asm volatile(
        "mma.sync.aligned.m16n8k8.row.col.f32.tf32.tf32.f32 "
        "{%0,%1,%2,%3}, {%4,%5,%6,%7}, {%8,%9}, {%0,%1,%2,%3};"
        : "+f"(c[0]), "+f"(c[1]), "+f"(c[2]), "+f"(c[3])
        : "r"(a0), "r"(a1), "r"(a2), "r"(a3), "r"(b0), "r"(b1));
}
__device__ __forceinline__ void cp_async4(uint32_t dst, const void* src, bool ok) {
    int sz = ok ? 4 : 0;
    asm volatile("cp.async.ca.shared.global [%0], [%1], 4, %2;"
                 :: "r"(dst), "l"(src), "r"(sz));
}
__device__ __forceinline__ void cp_commit() {
    asm volatile("cp.async.commit_group;" ::: "memory");
}
__device__ __forceinline__ void cp_wait1() {
    asm volatile("cp.async.wait_group 1;" ::: "memory");
}

extern __shared__ float dynsm[];

// ------------------------------------------------------- FP32 GEMM + bias
__global__ __launch_bounds__(256)
void gemm_bias_kernel(const float* __restrict__ A, const float* __restrict__ W,
                      const float* __restrict__ bias, float* __restrict__ C,
                      int M, int Nc, int K) {
    __shared__ float As[16][132];
    __shared__ float Ws[16][132];
    const int t  = threadIdx.x;
    const int tx = t & 15, ty = t >> 4;
    const int m0 = blockIdx.y * 128, n0 = blockIdx.x * 128;
    const int ar = t >> 1, kg = (t & 1) * 8;
    const int kr = t >> 4, wc = (t & 15) * 4;

    float acc[8][8] = {};
    for (int k0 = 0; k0 < K; k0 += 16) {
        float4 a0 = make_float4(0.f,0.f,0.f,0.f), a1 = a0;
        if (m0 + ar < M) {
            const float* p = &A[(size_t)(m0 + ar) * K + k0 + kg];
            a0 = *(const float4*)p; a1 = *(const float4*)(p + 4);
        }
        As[kg+0][ar] = a0.x; As[kg+1][ar] = a0.y; As[kg+2][ar] = a0.z; As[kg+3][ar] = a0.w;
        As[kg+4][ar] = a1.x; As[kg+5][ar] = a1.y; As[kg+6][ar] = a1.z; As[kg+7][ar] = a1.w;
        const float* wp = &W[(size_t)(k0 + kr) * Nc + n0];
        *(float4*)&Ws[kr][wc]      = *(const float4*)(wp + wc);
        *(float4*)&Ws[kr][wc + 64] = *(const float4*)(wp + wc + 64);
        __syncthreads();
        #pragma unroll
        for (int kk = 0; kk < 16; kk++) {
            float a[8], b[8];
            *(float4*)&a[0] = *(float4*)&As[kk][ty*8];
            *(float4*)&a[4] = *(float4*)&As[kk][ty*8+4];
            *(float4*)&b[0] = *(float4*)&Ws[kk][tx*8];
            *(float4*)&b[4] = *(float4*)&Ws[kk][tx*8+4];
            #pragma unroll
            for (int i = 0; i < 8; i++)
                #pragma unroll
                for (int j = 0; j < 8; j++)
                    acc[i][j] = fmaf(a[i], b[j], acc[i][j]);
        }
        __syncthreads();
    }
    #pragma unroll
    for (int i = 0; i < 8; i++) {
        int gr = m0 + ty*8 + i;
        if (gr >= M) continue;
        float* cp = &C[(size_t)gr * Nc + n0 + tx*8];
        const float* bp = &bias[n0 + tx*8];
        float4 r0, r1;
        r0.x = acc[i][0]+bp[0]; r0.y = acc[i][1]+bp[1]; r0.z = acc[i][2]+bp[2]; r0.w = acc[i][3]+bp[3];
        r1.x = acc[i][4]+bp[4]; r1.y = acc[i][5]+bp[5]; r1.z = acc[i][6]+bp[6]; r1.w = acc[i][7]+bp[7];
        *(float4*)cp = r0; *(float4*)(cp+4) = r1;
    }
}

// ------------------------------- tf32 mma.sync QK^T + fused segment partials
__global__ __launch_bounds__(256)
void qk_kernel(const float* __restrict__ qkv, float* __restrict__ A_raw,
               float* __restrict__ part) {
    const int t = threadIdx.x, lane = t & 31, wid = t >> 5;
    const int wrow = wid >> 2, wcol = wid & 3;
    const int bh = blockIdx.z, b = bh >> 3, h = bh & 7;
    const int n0 = blockIdx.y * 128;
    const int mtile = blockIdx.x, m0 = mtile * 128;

    uint32_t* qs = (uint32_t*)dynsm;       // [128][68] tf32 bits
    uint32_t* ks = qs + 128 * 68;
    float* res = dynsm;                    // output bounce alias [128][132]

    const float* qb = qkv + (size_t)b * cN * cE3 + h * 64;
    const float* kb = qb + cE;

    #pragma unroll
    for (int i = 0; i < 8; i++) {
        int idx = t + i * 256;
        int row = idx >> 4, q4 = idx & 15;
        float4 qv = make_float4(0.f,0.f,0.f,0.f), kv = qv;
        if (n0 + row < cN) qv = *(const float4*)&qb[(size_t)(n0+row)*cE3 + q4*4];
        if (m0 + row < cN) kv = *(const float4*)&kb[(size_t)(m0+row)*cE3 + q4*4];
        uint4 qu = make_uint4(f2tf32(qv.x), f2tf32(qv.y), f2tf32(qv.z), f2tf32(qv.w));
        uint4 ku = make_uint4(f2tf32(kv.x), f2tf32(kv.y), f2tf32(kv.z), f2tf32(kv.w));
        *(uint4*)&qs[row*68 + q4*4] = qu;
        *(uint4*)&ks[row*68 + q4*4] = ku;
    }
    __syncthreads();

    float acc[4][4][4] = {};
    #pragma unroll
    for (int kk = 0; kk < 8; kk++) {
        const int k0 = kk * 8;
        uint32_t a[4][4], bq[4][2];
        #pragma unroll
        for (int mt = 0; mt < 4; mt++) {
            int r = wrow*64 + mt*16 + (lane >> 2);
            a[mt][0] = qs[r*68     + k0     + (lane & 3)];
            a[mt][1] = qs[(r+8)*68 + k0     + (lane & 3)];
            a[mt][2] = qs[r*68     + k0 + 4 + (lane & 3)];
            a[mt][3] = qs[(r+8)*68 + k0 + 4 + (lane & 3)];
        }
        #pragma unroll
        for (int nt = 0; nt < 4; nt++) {
            int cc = wcol*32 + nt*8 + (lane >> 2);
            bq[nt][0] = ks[cc*68 + k0     + (lane & 3)];
            bq[nt][1] = ks[cc*68 + k0 + 4 + (lane & 3)];
        }
        #pragma unroll
        for (int mt = 0; mt < 4; mt++)
            #pragma unroll
            for (int nt = 0; nt < 4; nt++)
                mma_tf32(acc[mt][nt], a[mt][0], a[mt][1], a[mt][2], a[mt][3],
                         bq[nt][0], bq[nt][1]);
    }
    __syncthreads();

    #pragma unroll
    for (int mt = 0; mt < 4; mt++) {
        int r = wrow*64 + mt*16 + (lane >> 2);
        #pragma unroll
        for (int nt = 0; nt < 4; nt++) {
            int cc = wcol*32 + nt*8 + (lane & 3)*2;
            *(float2*)&res[r*132 + cc]     = make_float2(acc[mt][nt][0], acc[mt][nt][1]);
            *(float2*)&res[(r+8)*132 + cc] = make_float2(acc[mt][nt][2], acc[mt][nt][3]);
        }
    }
    __syncthreads();

    {
        int row = t >> 1, cbase = (t & 1) * 64;
        float sp = 0.f, sep = 0.f, st = 0.f, set = 0.f, vc = 0.f;
        if (n0 + row < cN) {
            if (mtile < 16) {
                #pragma unroll 4
                for (int j = 0; j < 64; j++) {
                    float v = res[row*132 + cbase + j] * SCALE_QK;
                    sp += v; sep += __expf(v);
                }
            } else if (cbase == 0) {
                for (int j = 0; j < 16; j++) {
                    float v = res[row*132 + j] * SCALE_QK;
                    st += v; set += __expf(v);
                }
                vc = res[row*132 + 16] * SCALE_QK;
            }
        }
        sp  += __shfl_xor_sync(0xffffffffu, sp,  1);
        sep += __shfl_xor_sync(0xffffffffu, sep, 1);
        st  += __shfl_xor_sync(0xffffffffu, st,  1);
        set += __shfl_xor_sync(0xffffffffu, set, 1);
        vc  += __shfl_xor_sync(0xffffffffu, vc,  1);
        if (!(t & 1) && (n0 + row) < cN) {
            float* pp = &part[((size_t)bh * PROWS + n0 + row) * PSTR + mtile * 4];
            pp[0] = sp; pp[1] = sep; pp[2] = st; pp[3] = set;
            if (mtile == 16)
                part[((size_t)bh * PROWS + n0 + row) * PSTR + 68] = vc;
        }
    }

    const size_t arbase = (size_t)bh * cN * cN;
    for (int i = 0; i < 64; i++) {
        int idx = t + i * 256;
        int r = idx >> 7, c = idx & 127;
        int gr = n0 + r, gc = m0 + c;
        if (gr < cN && gc < cN)
            A_raw[arbase + (size_t)gr * cN + gc] = res[r*132 + c] * SCALE_QK;
    }
}

// ------------------------------------------------------------ finalize fac
__global__ void finalize_kernel(const float* __restrict__ part, float* __restrict__ fac) {
    int idx = blockIdx.x * 256 + threadIdx.x;
    if (idx >= NBH * cN) return;
    int bh = idx / cN, n = idx - bh * cN;
    const float* p = part + ((size_t)bh * PROWS + n) * PSTR;
    float SP = 0.f, SEP = 0.f, ST = 0.f, SET = 0.f;
    #pragma unroll
    for (int mt = 0; mt < 17; mt++) {
        SP += p[mt*4]; SEP += p[mt*4+1]; ST += p[mt*4+2]; SET += p[mt*4+3];
    }
    float vc = p[68];
    float ep = __expf(SP * (1.f / (float)cNP));
    float et = __expf(ST * (1.f / (float)cNT));
    float ec = __expf(vc);
    float s = ep + et + ec;
    float* fp = &fac[(size_t)idx * 4];
    fp[0] = (ep / s) / (SEP + EPS_BAL);
    fp[1] = (et / s) / (SET + EPS_BAL);
    fp[2] = (ec / s) / (ec  + EPS_BAL);
    fp[3] = 0.f;
}

// --------------------------------------- streaming A materialization
// One block per (bh,n) row: A = exp(A_raw) * fac[seg]. 33040 blocks.
__global__ __launch_bounds__(256)
void mat_kernel(const float* __restrict__ A_raw, const float* __restrict__ fac,
                float* __restrict__ A) {
    const size_t row = blockIdx.x;
    const float* src = A_raw + row * cN;
    float* dst = A + row * cN;
    const float4 f = *(const float4*)&fac[row * 4];
    const int t = threadIdx.x;
    #pragma unroll
    for (int i = 0; i < 8; i++) {
        int idx = t + i * 256;               // 0..2047: patch segment
        dst[idx] = __expf(src[idx]) * f.x;
    }
    if (t < 17) {
        int idx = cNP + t;
        float ff = (t < 16) ? f.y : f.z;
        dst[idx] = __expf(src[idx]) * ff;
    }
}

// --------------------- tf32 AV GEMM, cp.async double-buffered (reads A)
// Block: 128(n) x 64(d). 8 warps = 4(n) x 2(d); warp tile 32x32. k-chunk 64.
__global__ __launch_bounds__(256)
void avg_kernel(const float* __restrict__ A, const float* __restrict__ qkv,
                float* __restrict__ OH) {
    const int t = threadIdx.x, lane = t & 31, wid = t >> 5;
    const int wrow = wid >> 1, wcol = wid & 1;
    const int bh = blockIdx.y, b = bh >> 3, h = bh & 7;
    const int n0 = blockIdx.x * 128;

    float* Ab = dynsm;                      // [2][128][68] fp32
    float* Vb = dynsm + 2 * 128 * 68;       // [2][64][68]  V^T: [d][m]
    const uint32_t sAb = (uint32_t)__cvta_generic_to_shared(Ab);

    const float* Arow = A + (size_t)bh * cN * cN;
    const float* vb = qkv + (size_t)b * cN * cE3 + 2 * cE + h * 64;

    // V stage coords: d = t&63, mgroup = t>>6 (4 groups of 16 m each)
    const int vd = t & 63, vmg = t >> 6;

    // ---- stage helpers (inlined manually in loop) ----
    float acc[2][4][4] = {};

    // prologue: stage chunk 0
    {
        const int m0 = 0;
        #pragma unroll
        for (int i = 0; i < 32; i++) {
            int idx = t + i * 256;
            int row = idx >> 6, col = idx & 63;
            int n = n0 + row, m = m0 + col;
            bool ok = (n < cN) && (m < cN);
            const float* src = &Arow[(size_t)(ok ? n : 0) * cN + (ok ? m : 0)];
            cp_async4(sAb + (uint32_t)((row*68 + col) * 4), src, ok);
        }
        float* Vd = Vb + vd * 68;
        #pragma unroll
        for (int j = 0; j < 4; j++) {
            int ml = vmg * 16 + j * 4;
            float4 v;
            v.x = (m0+ml+0 < cN) ? vb[(size_t)(m0+ml+0)*cE3 + vd] : 0.f;
            v.y = (m0+ml+1 < cN) ? vb[(size_t)(m0+ml+1)*cE3 + vd] : 0.f;
            v.z = (m0+ml+2 < cN) ? vb[(size_t)(m0+ml+2)*cE3 + vd] : 0.f;
            v.w = (m0+ml+3 < cN) ? vb[(size_t)(m0+ml+3)*cE3 + vd] : 0.f;
            *(float4*)&Vd[ml] = v;
        }
    }
    cp_commit();

    for (int c = 0; c < NCH; c++) {
        // stage chunk c+1 into buffer (c+1)&1
        if (c + 1 < NCH) {
            const int m0 = (c + 1) * 64;
            const uint32_t bufo = (uint32_t)(((c + 1) & 1) * 128 * 68 * 4);
            #pragma unroll
            for (int i = 0; i < 32; i++) {
                int idx = t + i * 256;
                int row = idx >> 6, col = idx & 63;
                int n = n0 + row, m = m0 + col;
                bool ok = (n < cN) && (m < cN);
                const float* src = &Arow[(size_t)(ok ? n : 0) * cN + (ok ? m : 0)];
                cp_async4(sAb + bufo + (uint32_t)((row*68 + col) * 4), src, ok);
            }
            float* Vd = Vb + ((c + 1) & 1) * 64 * 68 + vd * 68;
            #pragma unroll
            for (int j = 0; j < 4; j++) {
                int ml = vmg * 16 + j * 4;
                float4 v;
                v.x = (m0+ml+0 < cN) ? vb[(size_t)(m0+ml+0)*cE3 + vd] : 0.f;
                v.y = (m0+ml+1 < cN) ? vb[(size_t)(m0+ml+1)*cE3 + vd] : 0.f;
                v.z = (m0+ml+2 < cN) ? vb[(size_t)(m0+ml+2)*cE3 + vd] : 0.f;
                v.w = (m0+ml+3 < cN) ? vb[(size_t)(m0+ml+3)*cE3 + vd] : 0.f;
                *(float4*)&Vd[ml] = v;
            }
        }
        cp_commit();
        cp_wait1();
        __syncthreads();

        const float* Ac = Ab + (c & 1) * 128 * 68;
        const float* Vc = Vb + (c & 1) * 64 * 68;
        #pragma unroll
        for (int kk = 0; kk < 8; kk++) {
            const int k0 = kk * 8;
            uint32_t a[2][4], bq[4][2];
            #pragma unroll
            for (int mt = 0; mt < 2; mt++) {
                int r = wrow*32 + mt*16 + (lane >> 2);
                a[mt][0] = f2tf32(Ac[r*68     + k0     + (lane & 3)]);
                a[mt][1] = f2tf32(Ac[(r+8)*68 + k0     + (lane & 3)]);
                a[mt][2] = f2tf32(Ac[r*68     + k0 + 4 + (lane & 3)]);
                a[mt][3] = f2tf32(Ac[(r+8)*68 + k0 + 4 + (lane & 3)]);
            }
            #pragma unroll
            for (int nt = 0; nt < 4; nt++) {
                int dd = wcol*32 + nt*8 + (lane >> 2);
                bq[nt][0] = f2tf32(Vc[dd*68 + k0     + (lane & 3)]);
                bq[nt][1] = f2tf32(Vc[dd*68 + k0 + 4 + (lane & 3)]);
            }
            #pragma unroll
            for (int mt = 0; mt < 2; mt++)
                #pragma unroll
                for (int nt = 0; nt < 4; nt++)
                    mma_tf32(acc[mt][nt], a[mt][0], a[mt][1], a[mt][2], a[mt][3],
                             bq[nt][0], bq[nt][1]);
        }
        __syncthreads();
    }

    #pragma unroll
    for (int mt = 0; mt < 2; mt++) {
        #pragma unroll
        for (int nt = 0; nt < 4; nt++) {
            int n = n0 + wrow*32 + mt*16 + (lane >> 2);
            int d = wcol*32 + nt*8 + (lane & 3)*2;
            if (n < cN)
                *(float2*)&OH[((size_t)b * cN + n) * cE + h*64 + d] =
                    make_float2(acc[mt][nt][0], acc[mt][nt][1]);
            if (n + 8 < cN)
                *(float2*)&OH[((size_t)b * cN + n + 8) * cE + h*64 + d] =
                    make_float2(acc[mt][nt][2], acc[mt][nt][3]);
        }
    }
}

// ---------------------------------------------------------------------------
extern "C" void kernel_launch(void* const* d_in, const int* in_sizes, int n_in,
                              void* d_out, int out_size) {
    const float* x     = (const float*)d_in[0];
    const float* w_qkv = (const float*)d_in[1];
    const float* b_qkv = (const float*)d_in[2];
    const float* w_out = (const float*)d_in[3];
    const float* b_out = (const float*)d_in[4];

    float* out   = (float*)d_out;
    float* A     = out + (size_t)cB * cN * cE;
    float* A_raw = A   + (size_t)NBH * cN * cN;

    float *qkv = nullptr, *oh = nullptr, *facp = nullptr, *partp = nullptr;
    cudaGetSymbolAddress((void**)&qkv,   g_qkv);
    cudaGetSymbolAddress((void**)&oh,    g_oh);
    cudaGetSymbolAddress((void**)&facp,  g_fac);
    cudaGetSymbolAddress((void**)&partp, g_part);

    const int M = cB * cN;
    const int QK_SMEM  = 2 * 128 * 68 * 4;                 // 69632 B
    const int AVG_SMEM = (2*128*68 + 2*64*68) * 4;         // 104448 B
    cudaFuncSetAttribute(qk_kernel,  cudaFuncAttributeMaxDynamicSharedMemorySize, QK_SMEM);
    cudaFuncSetAttribute(avg_kernel, cudaFuncAttributeMaxDynamicSharedMemorySize, AVG_SMEM);

    gemm_bias_kernel<<<dim3(cE3/128, (M+127)/128), 256>>>(x, w_qkv, b_qkv, qkv, M, cE3, cE);
    qk_kernel<<<dim3(17, 17, NBH), 256, QK_SMEM>>>(qkv, A_raw, partp);
    finalize_kernel<<<(NBH*cN + 255)/256, 256>>>(partp, facp);
    mat_kernel<<<NBH * cN, 256>>>(A_raw, facp, A);
    avg_kernel<<<dim3(17, NBH), 256, AVG_SMEM>>>(A, qkv, oh);
    gemm_bias_kernel<<<dim3(cE/128, (M+127)/128), 256>>>(oh, w_out, b_out, out, M, cE, cE);
}

// round 7
// speedup vs baseline: 2.1962x; 1.2413x over previous
#include <cuda_runtime.h>
#include <cstdint>

#define cB  2
#define cN  2065
#define cNP 2048
#define cNT 16
#define cE  512
#define cH  8
#define cE3 1536
#define NBH (cB*cH)
#define SCALE_QK 0.125f
#define EPS_BAL  1e-6f
#define PROWS 2176
#define PSTR  72
#define NCH   33     // ceil(2065/64) k-chunks in avg

__device__ float g_qkv [(size_t)cB * cN * cE3];
__device__ float g_oh  [(size_t)cB * cN * cE];
__device__ float g_fac [(size_t)NBH * cN * 4];
__device__ float g_part[(size_t)NBH * PROWS * PSTR];

__device__ __forceinline__ uint32_t f2tf32(float x) {
    uint32_t r; asm("cvt.rna.tf32.f32 %0, %1;" : "=r"(r) : "f"(x)); return r;
}
__device__ __forceinline__ void mma_tf32(float* c, uint32_t a0, uint32_t a1,
                                         uint32_t a2, uint32_t a3,
                                         uint32_t b0, uint32_t b1) {
    asm volatile(
        "mma.sync.aligned.m16n8k8.row.col.f32.tf32.tf32.f32 "
        "{%0,%1,%2,%3}, {%4,%5,%6,%7}, {%8,%9}, {%0,%1,%2,%3};"
        : "+f"(c[0]), "+f"(c[1]), "+f"(c[2]), "+f"(c[3])
        : "r"(a0), "r"(a1), "r"(a2), "r"(a3), "r"(b0), "r"(b1));
}
__device__ __forceinline__ void cp_async4(uint32_t dst, const void* src, bool ok) {
    int sz = ok ? 4 : 0;
    asm volatile("cp.async.ca.shared.global [%0], [%1], 4, %2;"
                 :: "r"(dst), "l"(src), "r"(sz));
}
__device__ __forceinline__ void cp_commit() {
    asm volatile("cp.async.commit_group;" ::: "memory");
}
__device__ __forceinline__ void cp_wait1() {
    asm volatile("cp.async.wait_group 1;" ::: "memory");
}

extern __shared__ float dynsm[];

// --------------------- tf32 GEMM + bias (projections): C = A@W + bias
// Block 128(m)x128(n), 8 warps = 2(m)x4(n), warp tile 64x32. k-chunk 32,
// register-prefetch pipelining. Requires K%32==0, Nc%128==0.
__global__ __launch_bounds__(256)
void gemm_tf32_bias(const float* __restrict__ A, const float* __restrict__ W,
                    const float* __restrict__ bias, float* __restrict__ C,
                    int M, int Nc, int K) {
    __shared__ uint32_t As[128 * 36];   // [m][k] tf32 bits
    __shared__ uint32_t Ws[128 * 36];   // [n][k] tf32 bits (W transposed)
    const int t = threadIdx.x, lane = t & 31, wid = t >> 5;
    const int wrow = wid >> 2, wcol = wid & 3;
    const int m0 = blockIdx.y * 128, n0 = blockIdx.x * 128;

    // A loads: 128 rows x 8 float4; W loads: 32 rows x 32 float4
    const int arow = t >> 3, acol = (t & 7) * 4;   // +32 rows per i
    const int wrk  = t >> 5, wcn  = (t & 31) * 4;  // +8 rows per i

    float4 ra[4], rw[4];
    const int nchunks = K >> 5;

    // prologue: chunk 0
    #pragma unroll
    for (int i = 0; i < 4; i++) {
        int r = arow + i * 32;
        ra[i] = (m0 + r < M) ? *(const float4*)&A[(size_t)(m0 + r) * K + acol]
                             : make_float4(0.f, 0.f, 0.f, 0.f);
        rw[i] = *(const float4*)&W[(size_t)(wrk + i * 8) * Nc + n0 + wcn];
    }

    float acc[4][4][4] = {};

    for (int c = 0; c < nchunks; c++) {
        __syncthreads();
        #pragma unroll
        for (int i = 0; i < 4; i++) {
            int r = arow + i * 32;
            *(uint4*)&As[r * 36 + acol] =
                make_uint4(f2tf32(ra[i].x), f2tf32(ra[i].y), f2tf32(ra[i].z), f2tf32(ra[i].w));
            int k = wrk + i * 8;
            Ws[(wcn + 0) * 36 + k] = f2tf32(rw[i].x);
            Ws[(wcn + 1) * 36 + k] = f2tf32(rw[i].y);
            Ws[(wcn + 2) * 36 + k] = f2tf32(rw[i].z);
            Ws[(wcn + 3) * 36 + k] = f2tf32(rw[i].w);
        }
        __syncthreads();

        if (c + 1 < nchunks) {
            const int k0c = (c + 1) * 32;
            #pragma unroll
            for (int i = 0; i < 4; i++) {
                int r = arow + i * 32;
                ra[i] = (m0 + r < M) ? *(const float4*)&A[(size_t)(m0 + r) * K + k0c + acol]
                                     : make_float4(0.f, 0.f, 0.f, 0.f);
                rw[i] = *(const float4*)&W[(size_t)(k0c + wrk + i * 8) * Nc + n0 + wcn];
            }
        }

        #pragma unroll
        for (int kk = 0; kk < 4; kk++) {
            const int k0 = kk * 8;
            uint32_t a[4][4], bq[4][2];
            #pragma unroll
            for (int mt = 0; mt < 4; mt++) {
                int r = wrow*64 + mt*16 + (lane >> 2);
                a[mt][0] = As[r*36     + k0     + (lane & 3)];
                a[mt][1] = As[(r+8)*36 + k0     + (lane & 3)];
                a[mt][2] = As[r*36     + k0 + 4 + (lane & 3)];
                a[mt][3] = As[(r+8)*36 + k0 + 4 + (lane & 3)];
            }
            #pragma unroll
            for (int nt = 0; nt < 4; nt++) {
                int cc = wcol*32 + nt*8 + (lane >> 2);
                bq[nt][0] = Ws[cc*36 + k0     + (lane & 3)];
                bq[nt][1] = Ws[cc*36 + k0 + 4 + (lane & 3)];
            }
            #pragma unroll
            for (int mt = 0; mt < 4; mt++)
                #pragma unroll
                for (int nt = 0; nt < 4; nt++)
                    mma_tf32(acc[mt][nt], a[mt][0], a[mt][1], a[mt][2], a[mt][3],
                             bq[nt][0], bq[nt][1]);
        }
    }

    #pragma unroll
    for (int mt = 0; mt < 4; mt++) {
        #pragma unroll
        for (int nt = 0; nt < 4; nt++) {
            int gr = m0 + wrow*64 + mt*16 + (lane >> 2);
            int gc = n0 + wcol*32 + nt*8 + (lane & 3) * 2;
            float b0 = bias[gc], b1 = bias[gc + 1];
            if (gr < M)
                *(float2*)&C[(size_t)gr * Nc + gc] =
                    make_float2(acc[mt][nt][0] + b0, acc[mt][nt][1] + b1);
            if (gr + 8 < M)
                *(float2*)&C[(size_t)(gr + 8) * Nc + gc] =
                    make_float2(acc[mt][nt][2] + b0, acc[mt][nt][3] + b1);
        }
    }
}

// ------------------------------- tf32 mma.sync QK^T + fused segment partials
__global__ __launch_bounds__(256)
void qk_kernel(const float* __restrict__ qkv, float* __restrict__ A_raw,
               float* __restrict__ part) {
    const int t = threadIdx.x, lane = t & 31, wid = t >> 5;
    const int wrow = wid >> 2, wcol = wid & 3;
    const int bh = blockIdx.z, b = bh >> 3, h = bh & 7;
    const int n0 = blockIdx.y * 128;
    const int mtile = blockIdx.x, m0 = mtile * 128;

    uint32_t* qs = (uint32_t*)dynsm;       // [128][68] tf32 bits
    uint32_t* ks = qs + 128 * 68;
    float* res = dynsm;                    // output bounce alias [128][132]

    const float* qb = qkv + (size_t)b * cN * cE3 + h * 64;
    const float* kb = qb + cE;

    #pragma unroll
    for (int i = 0; i < 8; i++) {
        int idx = t + i * 256;
        int row = idx >> 4, q4 = idx & 15;
        float4 qv = make_float4(0.f,0.f,0.f,0.f), kv = qv;
        if (n0 + row < cN) qv = *(const float4*)&qb[(size_t)(n0+row)*cE3 + q4*4];
        if (m0 + row < cN) kv = *(const float4*)&kb[(size_t)(m0+row)*cE3 + q4*4];
        uint4 qu = make_uint4(f2tf32(qv.x), f2tf32(qv.y), f2tf32(qv.z), f2tf32(qv.w));
        uint4 ku = make_uint4(f2tf32(kv.x), f2tf32(kv.y), f2tf32(kv.z), f2tf32(kv.w));
        *(uint4*)&qs[row*68 + q4*4] = qu;
        *(uint4*)&ks[row*68 + q4*4] = ku;
    }
    __syncthreads();

    float acc[4][4][4] = {};
    #pragma unroll
    for (int kk = 0; kk < 8; kk++) {
        const int k0 = kk * 8;
        uint32_t a[4][4], bq[4][2];
        #pragma unroll
        for (int mt = 0; mt < 4; mt++) {
            int r = wrow*64 + mt*16 + (lane >> 2);
            a[mt][0] = qs[r*68     + k0     + (lane & 3)];
            a[mt][1] = qs[(r+8)*68 + k0     + (lane & 3)];
            a[mt][2] = qs[r*68     + k0 + 4 + (lane & 3)];
            a[mt][3] = qs[(r+8)*68 + k0 + 4 + (lane & 3)];
        }
        #pragma unroll
        for (int nt = 0; nt < 4; nt++) {
            int cc = wcol*32 + nt*8 + (lane >> 2);
            bq[nt][0] = ks[cc*68 + k0     + (lane & 3)];
            bq[nt][1] = ks[cc*68 + k0 + 4 + (lane & 3)];
        }
        #pragma unroll
        for (int mt = 0; mt < 4; mt++)
            #pragma unroll
            for (int nt = 0; nt < 4; nt++)
                mma_tf32(acc[mt][nt], a[mt][0], a[mt][1], a[mt][2], a[mt][3],
                         bq[nt][0], bq[nt][1]);
    }
    __syncthreads();

    #pragma unroll
    for (int mt = 0; mt < 4; mt++) {
        int r = wrow*64 + mt*16 + (lane >> 2);
        #pragma unroll
        for (int nt = 0; nt < 4; nt++) {
            int cc = wcol*32 + nt*8 + (lane & 3)*2;
            *(float2*)&res[r*132 + cc]     = make_float2(acc[mt][nt][0], acc[mt][nt][1]);
            *(float2*)&res[(r+8)*132 + cc] = make_float2(acc[mt][nt][2], acc[mt][nt][3]);
        }
    }
    __syncthreads();

    {
        int row = t >> 1, cbase = (t & 1) * 64;
        float sp = 0.f, sep = 0.f, st = 0.f, set = 0.f, vc = 0.f;
        if (n0 + row < cN) {
            if (mtile < 16) {
                #pragma unroll 4
                for (int j = 0; j < 64; j++) {
                    float v = res[row*132 + cbase + j] * SCALE_QK;
                    sp += v; sep += __expf(v);
                }
            } else if (cbase == 0) {
                for (int j = 0; j < 16; j++) {
                    float v = res[row*132 + j] * SCALE_QK;
                    st += v; set += __expf(v);
                }
                vc = res[row*132 + 16] * SCALE_QK;
            }
        }
        sp  += __shfl_xor_sync(0xffffffffu, sp,  1);
        sep += __shfl_xor_sync(0xffffffffu, sep, 1);
        st  += __shfl_xor_sync(0xffffffffu, st,  1);
        set += __shfl_xor_sync(0xffffffffu, set, 1);
        vc  += __shfl_xor_sync(0xffffffffu, vc,  1);
        if (!(t & 1) && (n0 + row) < cN) {
            float* pp = &part[((size_t)bh * PROWS + n0 + row) * PSTR + mtile * 4];
            pp[0] = sp; pp[1] = sep; pp[2] = st; pp[3] = set;
            if (mtile == 16)
                part[((size_t)bh * PROWS + n0 + row) * PSTR + 68] = vc;
        }
    }

    const size_t arbase = (size_t)bh * cN * cN;
    for (int i = 0; i < 64; i++) {
        int idx = t + i * 256;
        int r = idx >> 7, c = idx & 127;
        int gr = n0 + r, gc = m0 + c;
        if (gr < cN && gc < cN)
            A_raw[arbase + (size_t)gr * cN + gc] = res[r*132 + c] * SCALE_QK;
    }
}

// ------------------------------------------------------------ finalize fac
__global__ void finalize_kernel(const float* __restrict__ part, float* __restrict__ fac) {
    int idx = blockIdx.x * 256 + threadIdx.x;
    if (idx >= NBH * cN) return;
    int bh = idx / cN, n = idx - bh * cN;
    const float* p = part + ((size_t)bh * PROWS + n) * PSTR;
    float SP = 0.f, SEP = 0.f, ST = 0.f, SET = 0.f;
    #pragma unroll
    for (int mt = 0; mt < 17; mt++) {
        SP += p[mt*4]; SEP += p[mt*4+1]; ST += p[mt*4+2]; SET += p[mt*4+3];
    }
    float vc = p[68];
    float ep = __expf(SP * (1.f / (float)cNP));
    float et = __expf(ST * (1.f / (float)cNT));
    float ec = __expf(vc);
    float s = ep + et + ec;
    float* fp = &fac[(size_t)idx * 4];
    fp[0] = (ep / s) / (SEP + EPS_BAL);
    fp[1] = (et / s) / (SET + EPS_BAL);
    fp[2] = (ec / s) / (ec  + EPS_BAL);
    fp[3] = 0.f;
}

// --------------------------------------- streaming A materialization
__global__ __launch_bounds__(256)
void mat_kernel(const float* __restrict__ A_raw, const float* __restrict__ fac,
                float* __restrict__ A) {
    const size_t row = blockIdx.x;
    const float* src = A_raw + row * cN;
    float* dst = A + row * cN;
    const float4 f = *(const float4*)&fac[row * 4];
    const int t = threadIdx.x;
    #pragma unroll
    for (int i = 0; i < 8; i++) {
        int idx = t + i * 256;
        dst[idx] = __expf(src[idx]) * f.x;
    }
    if (t < 17) {
        int idx = cNP + t;
        float ff = (t < 16) ? f.y : f.z;
        dst[idx] = __expf(src[idx]) * ff;
    }
}

// --------------------- tf32 AV GEMM, cp.async double-buffered (reads A)
__global__ __launch_bounds__(256)
void avg_kernel(const float* __restrict__ A, const float* __restrict__ qkv,
                float* __restrict__ OH) {
    const int t = threadIdx.x, lane = t & 31, wid = t >> 5;
    const int wrow = wid >> 1, wcol = wid & 1;
    const int bh = blockIdx.y, b = bh >> 3, h = bh & 7;
    const int n0 = blockIdx.x * 128;

    float* Ab = dynsm;                      // [2][128][68] fp32
    float* Vb = dynsm + 2 * 128 * 68;       // [2][64][68]  V^T: [d][m]
    const uint32_t sAb = (uint32_t)__cvta_generic_to_shared(Ab);

    const float* Arow = A + (size_t)bh * cN * cN;
    const float* vb = qkv + (size_t)b * cN * cE3 + 2 * cE + h * 64;

    const int vd = t & 63, vmg = t >> 6;
    float acc[2][4][4] = {};

    {
        const int m0 = 0;
        #pragma unroll
        for (int i = 0; i < 32; i++) {
            int idx = t + i * 256;
            int row = idx >> 6, col = idx & 63;
            int n = n0 + row, m = m0 + col;
            bool ok = (n < cN) && (m < cN);
            const float* src = &Arow[(size_t)(ok ? n : 0) * cN + (ok ? m : 0)];
            cp_async4(sAb + (uint32_t)((row*68 + col) * 4), src, ok);
        }
        float* Vd = Vb + vd * 68;
        #pragma unroll
        for (int j = 0; j < 4; j++) {
            int ml = vmg * 16 + j * 4;
            float4 v;
            v.x = (m0+ml+0 < cN) ? vb[(size_t)(m0+ml+0)*cE3 + vd] : 0.f;
            v.y = (m0+ml+1 < cN) ? vb[(size_t)(m0+ml+1)*cE3 + vd] : 0.f;
            v.z = (m0+ml+2 < cN) ? vb[(size_t)(m0+ml+2)*cE3 + vd] : 0.f;
            v.w = (m0+ml+3 < cN) ? vb[(size_t)(m0+ml+3)*cE3 + vd] : 0.f;
            *(float4*)&Vd[ml] = v;
        }
    }
    cp_commit();

    for (int c = 0; c < NCH; c++) {
        if (c + 1 < NCH) {
            const int m0 = (c + 1) * 64;
            const uint32_t bufo = (uint32_t)(((c + 1) & 1) * 128 * 68 * 4);
            #pragma unroll
            for (int i = 0; i < 32; i++) {
                int idx = t + i * 256;
                int row = idx >> 6, col = idx & 63;
                int n = n0 + row, m = m0 + col;
                bool ok = (n < cN) && (m < cN);
                const float* src = &Arow[(size_t)(ok ? n : 0) * cN + (ok ? m : 0)];
                cp_async4(sAb + bufo + (uint32_t)((row*68 + col) * 4), src, ok);
            }
            float* Vd = Vb + ((c + 1) & 1) * 64 * 68 + vd * 68;
            #pragma unroll
            for (int j = 0; j < 4; j++) {
                int ml = vmg * 16 + j * 4;
                float4 v;
                v.x = (m0+ml+0 < cN) ? vb[(size_t)(m0+ml+0)*cE3 + vd] : 0.f;
                v.y = (m0+ml+1 < cN) ? vb[(size_t)(m0+ml+1)*cE3 + vd] : 0.f;
                v.z = (m0+ml+2 < cN) ? vb[(size_t)(m0+ml+2)*cE3 + vd] : 0.f;
                v.w = (m0+ml+3 < cN) ? vb[(size_t)(m0+ml+3)*cE3 + vd] : 0.f;
                *(float4*)&Vd[ml] = v;
            }
        }
        cp_commit();
        cp_wait1();
        __syncthreads();

        const float* Ac = Ab + (c & 1) * 128 * 68;
        const float* Vc = Vb + (c & 1) * 64 * 68;
        #pragma unroll
        for (int kk = 0; kk < 8; kk++) {
            const int k0 = kk * 8;
            uint32_t a[2][4], bq[4][2];
            #pragma unroll
            for (int mt = 0; mt < 2; mt++) {
                int r = wrow*32 + mt*16 + (lane >> 2);
                a[mt][0] = f2tf32(Ac[r*68     + k0     + (lane & 3)]);
                a[mt][1] = f2tf32(Ac[(r+8)*68 + k0     + (lane & 3)]);
                a[mt][2] = f2tf32(Ac[r*68     + k0 + 4 + (lane & 3)]);
                a[mt][3] = f2tf32(Ac[(r+8)*68 + k0 + 4 + (lane & 3)]);
            }
            #pragma unroll
            for (int nt = 0; nt < 4; nt++) {
                int dd = wcol*32 + nt*8 + (lane >> 2);
                bq[nt][0] = f2tf32(Vc[dd*68 + k0     + (lane & 3)]);
                bq[nt][1] = f2tf32(Vc[dd*68 + k0 + 4 + (lane & 3)]);
            }
            #pragma unroll
            for (int mt = 0; mt < 2; mt++)
                #pragma unroll
                for (int nt = 0; nt < 4; nt++)
                    mma_tf32(acc[mt][nt], a[mt][0], a[mt][1], a[mt][2], a[mt][3],
                             bq[nt][0], bq[nt][1]);
        }
        __syncthreads();
    }

    #pragma unroll
    for (int mt = 0; mt < 2; mt++) {
        #pragma unroll
        for (int nt = 0; nt < 4; nt++) {
            int n = n0 + wrow*32 + mt*16 + (lane >> 2);
            int d = wcol*32 + nt*8 + (lane & 3)*2;
            if (n < cN)
                *(float2*)&OH[((size_t)b * cN + n) * cE + h*64 + d] =
                    make_float2(acc[mt][nt][0], acc[mt][nt][1]);
            if (n + 8 < cN)
                *(float2*)&OH[((size_t)b * cN + n + 8) * cE + h*64 + d] =
                    make_float2(acc[mt][nt][2], acc[mt][nt][3]);
        }
    }
}

// ---------------------------------------------------------------------------
extern "C" void kernel_launch(void* const* d_in, const int* in_sizes, int n_in,
                              void* d_out, int out_size) {
    const float* x     = (const float*)d_in[0];
    const float* w_qkv = (const float*)d_in[1];
    const float* b_qkv = (const float*)d_in[2];
    const float* w_out = (const float*)d_in[3];
    const float* b_out = (const float*)d_in[4];

    float* out   = (float*)d_out;
    float* A     = out + (size_t)cB * cN * cE;
    float* A_raw = A   + (size_t)NBH * cN * cN;

    float *qkv = nullptr, *oh = nullptr, *facp = nullptr, *partp = nullptr;
    cudaGetSymbolAddress((void**)&qkv,   g_qkv);
    cudaGetSymbolAddress((void**)&oh,    g_oh);
    cudaGetSymbolAddress((void**)&facp,  g_fac);
    cudaGetSymbolAddress((void**)&partp, g_part);

    const int M = cB * cN;
    const int QK_SMEM  = 2 * 128 * 68 * 4;                 // 69632 B
    const int AVG_SMEM = (2*128*68 + 2*64*68) * 4;         // 104448 B
    cudaFuncSetAttribute(qk_kernel,  cudaFuncAttributeMaxDynamicSharedMemorySize, QK_SMEM);
    cudaFuncSetAttribute(avg_kernel, cudaFuncAttributeMaxDynamicSharedMemorySize, AVG_SMEM);

    gemm_tf32_bias<<<dim3(cE3/128, (M+127)/128), 256>>>(x, w_qkv, b_qkv, qkv, M, cE3, cE);
    qk_kernel<<<dim3(17, 17, NBH), 256, QK_SMEM>>>(qkv, A_raw, partp);
    finalize_kernel<<<(NBH*cN + 255)/256, 256>>>(partp, facp);
    mat_kernel<<<NBH * cN, 256>>>(A_raw, facp, A);
    avg_kernel<<<dim3(17, NBH), 256, AVG_SMEM>>>(A, qkv, oh);
    gemm_tf32_bias<<<dim3(cE/128, (M+127)/128), 256>>>(oh, w_out, b_out, out, M, cE, cE);
}